// round 1
// baseline (speedup 1.0000x reference)
#include <cuda_runtime.h>
#include <cuda_bf16.h>
#include <math.h>

// Problem constants (fixed shapes per reference)
#define T_MAX 2048
#define HID   2048
#define NQ    32
#define NKV   8
#define HD    64
#define QKV_COLS ((NQ + 2*NKV) * HD)   // 3072
#define K_OFF (NQ * HD)                // 2048
#define V_OFF ((NQ + NKV) * HD)        // 2560

// Scratch (no allocation allowed)
__device__ float g_qkv[T_MAX * QKV_COLS];   // ~25 MB
__device__ float g_attn[T_MAX * NQ * HD];   // ~16 MB

// ---------------------------------------------------------------------------
// SGEMM: C[M,N] = A[M,K] @ B[K,N], row-major, M%128==0, N%128==0, K%8==0
// ---------------------------------------------------------------------------
#define BM 128
#define BN 128
#define BK 8
#define TM 8
#define TN 8

__global__ __launch_bounds__(256) void sgemm_kernel(
    const float* __restrict__ A, const float* __restrict__ B,
    float* __restrict__ C, int M, int N, int K)
{
    __shared__ float As[BK][BM];
    __shared__ float Bs[BK][BN];

    const int tid = threadIdx.x;
    const int bx = blockIdx.x;   // N tile
    const int by = blockIdx.y;   // M tile

    const float* Ab = A + (size_t)by * BM * K;
    const float* Bb = B + (size_t)bx * BN;

    float acc[TM][TN];
    #pragma unroll
    for (int i = 0; i < TM; i++)
        #pragma unroll
        for (int j = 0; j < TN; j++) acc[i][j] = 0.0f;

    const int arow = tid >> 1;          // 0..127
    const int acol = (tid & 1) * 4;     // 0 or 4
    const int brow = tid >> 5;          // 0..7
    const int bcol = (tid & 31) * 4;    // 0..124

    const int ty = tid >> 4;            // 0..15
    const int tx = tid & 15;            // 0..15

    for (int k0 = 0; k0 < K; k0 += BK) {
        float4 a4 = *(const float4*)(Ab + (size_t)arow * K + k0 + acol);
        As[acol + 0][arow] = a4.x;
        As[acol + 1][arow] = a4.y;
        As[acol + 2][arow] = a4.z;
        As[acol + 3][arow] = a4.w;
        float4 b4 = *(const float4*)(Bb + (size_t)(k0 + brow) * N + bcol);
        *(float4*)&Bs[brow][bcol] = b4;
        __syncthreads();

        #pragma unroll
        for (int k = 0; k < BK; k++) {
            float a[TM], b[TN];
            #pragma unroll
            for (int i = 0; i < TM; i++) a[i] = As[k][ty * TM + i];
            #pragma unroll
            for (int j = 0; j < TN; j++) b[j] = Bs[k][tx * TN + j];
            #pragma unroll
            for (int i = 0; i < TM; i++)
                #pragma unroll
                for (int j = 0; j < TN; j++)
                    acc[i][j] += a[i] * b[j];
        }
        __syncthreads();
    }

    float* Cb = C + (size_t)(by * BM + ty * TM) * N + bx * BN + tx * TN;
    #pragma unroll
    for (int i = 0; i < TM; i++) {
        #pragma unroll
        for (int j = 0; j < TN; j += 4) {
            float4 v = make_float4(acc[i][j], acc[i][j+1], acc[i][j+2], acc[i][j+3]);
            *(float4*)(Cb + (size_t)i * N + j) = v;
        }
    }
}

// ---------------------------------------------------------------------------
// RMSNorm (per head, D=64) + RoPE, in-place on g_qkv. grid=(NQ+NKV, T), blk=64
// ---------------------------------------------------------------------------
__global__ void rmsnorm_rope_kernel(
    float* __restrict__ qkv, const int* __restrict__ positions,
    const float* __restrict__ q_ln_w, const float* __restrict__ k_ln_w)
{
    const int head = blockIdx.x;
    const int t = blockIdx.y;
    const int d = threadIdx.x;

    float* base;
    const float* w;
    if (head < NQ) {
        base = qkv + (size_t)t * QKV_COLS + head * HD;
        w = q_ln_w;
    } else {
        base = qkv + (size_t)t * QKV_COLS + K_OFF + (head - NQ) * HD;
        w = k_ln_w;
    }

    float x = base[d];
    float ss = x * x;
    #pragma unroll
    for (int o = 16; o > 0; o >>= 1) ss += __shfl_xor_sync(0xffffffff, ss, o);

    __shared__ float sred[2];
    if ((d & 31) == 0) sred[d >> 5] = ss;
    __syncthreads();
    float sum = sred[0] + sred[1];

    float y = x * rsqrtf(sum * (1.0f / 64.0f) + 1e-5f) * w[d];

    __shared__ float sh[HD];
    sh[d] = y;
    __syncthreads();

    if (d < 32) {
        float x1 = sh[d];
        float x2 = sh[d + 32];
        float pos = (float)positions[t];
        float inv = powf(1000000.0f, -(float)d * (1.0f / 32.0f));
        float s, c;
        sincosf(pos * inv, &s, &c);
        base[d]      = x1 * c - x2 * s;
        base[d + 32] = x2 * c + x1 * s;
    }
}

// ---------------------------------------------------------------------------
// Flash-style causal GQA attention.
// grid = (T/128, NQ), block = 128. One query row per thread.
// ---------------------------------------------------------------------------
#define AT_BN 32

__global__ __launch_bounds__(128) void attn_kernel(
    const float* __restrict__ qkv, float* __restrict__ out, int T)
{
    const int qtile = blockIdx.x;
    const int h = blockIdx.y;
    const int kvh = h >> 2;      // G = NQ/NKV = 4
    const int tid = threadIdx.x;
    const int qi = qtile * 128 + tid;

    float q[HD];
    const float* qptr = qkv + (size_t)qi * QKV_COLS + h * HD;
    #pragma unroll
    for (int d = 0; d < HD; d++) q[d] = qptr[d];

    float o[HD];
    #pragma unroll
    for (int d = 0; d < HD; d++) o[d] = 0.0f;
    float m = -1e30f, l = 0.0f;

    __shared__ float Ks[AT_BN][HD];
    __shared__ float Vs[AT_BN][HD];

    const int nk = qtile * 128 + 128;   // keys needed for this block

    for (int k0 = 0; k0 < nk; k0 += AT_BN) {
        __syncthreads();
        // Load AT_BN x 64 K and V tiles: 512 float4s each / 128 threads -> 4 each
        #pragma unroll
        for (int r = 0; r < 4; r++) {
            int lin = (r * 128 + tid) * 4;   // element index in tile
            int row = lin >> 6;
            int col = lin & 63;
            const float* krow = qkv + (size_t)(k0 + row) * QKV_COLS + K_OFF + kvh * HD + col;
            const float* vrow = qkv + (size_t)(k0 + row) * QKV_COLS + V_OFF + kvh * HD + col;
            *(float4*)&Ks[row][col] = *(const float4*)krow;
            *(float4*)&Vs[row][col] = *(const float4*)vrow;
        }
        __syncthreads();

        float p[AT_BN];
        float mt = m;
        #pragma unroll 4
        for (int j = 0; j < AT_BN; j++) {
            float s0 = 0.f, s1 = 0.f, s2 = 0.f, s3 = 0.f;
            #pragma unroll
            for (int d = 0; d < HD; d += 4) {
                s0 += q[d + 0] * Ks[j][d + 0];
                s1 += q[d + 1] * Ks[j][d + 1];
                s2 += q[d + 2] * Ks[j][d + 2];
                s3 += q[d + 3] * Ks[j][d + 3];
            }
            float s = ((s0 + s1) + (s2 + s3)) * 0.125f;
            if (k0 + j > qi) s = -1e30f;
            p[j] = s;
            mt = fmaxf(mt, s);
        }

        float scale = __expf(m - mt);
        l *= scale;
        #pragma unroll
        for (int d = 0; d < HD; d++) o[d] *= scale;
        m = mt;

        #pragma unroll 4
        for (int j = 0; j < AT_BN; j++) {
            float pj = __expf(p[j] - mt);
            l += pj;
            #pragma unroll
            for (int d = 0; d < HD; d++)
                o[d] += pj * Vs[j][d];
        }
    }

    float invl = 1.0f / l;
    float* op = out + (size_t)qi * (NQ * HD) + h * HD;
    #pragma unroll
    for (int d = 0; d < HD; d++) op[d] = o[d] * invl;
}

// ---------------------------------------------------------------------------
// Launch
// ---------------------------------------------------------------------------
extern "C" void kernel_launch(void* const* d_in, const int* in_sizes, int n_in,
                              void* d_out, int out_size)
{
    const int*   positions = (const int*)d_in[0];
    const float* hidden    = (const float*)d_in[1];
    const float* w_qkv     = (const float*)d_in[2];
    const float* w_out     = (const float*)d_in[3];
    const float* q_ln_w    = (const float*)d_in[4];
    const float* k_ln_w    = (const float*)d_in[5];
    float* out = (float*)d_out;

    const int T = in_sizes[1] / HID;   // 2048

    float* qkv = nullptr;
    float* attn = nullptr;
    cudaGetSymbolAddress((void**)&qkv, g_qkv);
    cudaGetSymbolAddress((void**)&attn, g_attn);

    // 1) QKV projection: [T,HID] @ [HID,3072]
    {
        dim3 grid(QKV_COLS / BN, T / BM);
        sgemm_kernel<<<grid, 256>>>(hidden, w_qkv, qkv, T, QKV_COLS, HID);
    }

    // 2) RMSNorm + RoPE in-place on q and k heads
    {
        dim3 grid(NQ + NKV, T);
        rmsnorm_rope_kernel<<<grid, 64>>>(qkv, positions, q_ln_w, k_ln_w);
    }

    // 3) Causal GQA attention
    {
        dim3 grid(T / 128, NQ);
        attn_kernel<<<grid, 128>>>(qkv, attn, T);
    }

    // 4) Output projection: [T,2048] @ [2048,HID]
    {
        dim3 grid(HID / BN, T / BM);
        sgemm_kernel<<<grid, 256>>>(attn, w_out, out, T, HID, NQ * HD);
    }
}

// round 3
// speedup vs baseline: 1.5303x; 1.5303x over previous
#include <cuda_runtime.h>
#include <cuda_bf16.h>
#include <math.h>
#include <stdint.h>

// Problem constants (fixed shapes per reference)
#define T_MAX 2048
#define HID   2048
#define NQ    32
#define NKV   8
#define HD    64
#define QKV_COLS ((NQ + 2*NKV) * HD)   // 3072
#define K_OFF (NQ * HD)                // 2048
#define V_OFF ((NQ + NKV) * HD)        // 2560

// Scratch (no allocation allowed)
__device__ float g_qkv[T_MAX * QKV_COLS];
__device__ float g_attn[T_MAX * NQ * HD];

__device__ __nv_bfloat16 g_hid_hi[T_MAX * HID];
__device__ __nv_bfloat16 g_hid_lo[T_MAX * HID];
__device__ __nv_bfloat16 g_wqkv_hi[HID * QKV_COLS];
__device__ __nv_bfloat16 g_wqkv_lo[HID * QKV_COLS];
__device__ __nv_bfloat16 g_attn_hi[T_MAX * NQ * HD];
__device__ __nv_bfloat16 g_attn_lo[T_MAX * NQ * HD];
__device__ __nv_bfloat16 g_wout_hi[NQ * HD * HID];
__device__ __nv_bfloat16 g_wout_lo[NQ * HD * HID];

// ---------------------------------------------------------------------------
// PTX helpers
// ---------------------------------------------------------------------------
__device__ __forceinline__ void cp16(uint32_t dst, const void* src) {
    asm volatile("cp.async.cg.shared.global [%0], [%1], 16;" :: "r"(dst), "l"(src));
}
__device__ __forceinline__ void cp_commit() {
    asm volatile("cp.async.commit_group;");
}
__device__ __forceinline__ void cp_wait1() {
    asm volatile("cp.async.wait_group 1;");
}
__device__ __forceinline__ void ldm_x4(uint32_t* r, uint32_t a) {
    asm volatile("ldmatrix.sync.aligned.m8n8.x4.shared.b16 {%0,%1,%2,%3}, [%4];"
        : "=r"(r[0]), "=r"(r[1]), "=r"(r[2]), "=r"(r[3]) : "r"(a));
}
__device__ __forceinline__ void ldm_x4_t(uint32_t* r, uint32_t a) {
    asm volatile("ldmatrix.sync.aligned.m8n8.x4.trans.shared.b16 {%0,%1,%2,%3}, [%4];"
        : "=r"(r[0]), "=r"(r[1]), "=r"(r[2]), "=r"(r[3]) : "r"(a));
}
__device__ __forceinline__ void mma16816(float* c, const uint32_t* a, const uint32_t* b) {
    asm volatile(
        "mma.sync.aligned.m16n8k16.row.col.f32.bf16.bf16.f32 "
        "{%0,%1,%2,%3}, {%4,%5,%6,%7}, {%8,%9}, {%0,%1,%2,%3};"
        : "+f"(c[0]), "+f"(c[1]), "+f"(c[2]), "+f"(c[3])
        : "r"(a[0]), "r"(a[1]), "r"(a[2]), "r"(a[3]), "r"(b[0]), "r"(b[1]));
}
__device__ __forceinline__ uint32_t smem_u32(const void* p) {
    return (uint32_t)__cvta_generic_to_shared(p);
}

// ---------------------------------------------------------------------------
// Split fp32 -> (hi, lo) bf16 pair: x ~= hi + lo
// ---------------------------------------------------------------------------
__global__ __launch_bounds__(256) void split_kernel(
    const float* __restrict__ x, __nv_bfloat16* __restrict__ hi,
    __nv_bfloat16* __restrict__ lo, int n)
{
    int i = (blockIdx.x * 256 + threadIdx.x) * 4;
    if (i >= n) { return; }
    float4 v = *(const float4*)(x + i);
    float f0 = v.x;
    float f1 = v.y;
    float f2 = v.z;
    float f3 = v.w;
    __nv_bfloat16 h0 = __float2bfloat16_rn(f0);
    __nv_bfloat16 h1 = __float2bfloat16_rn(f1);
    __nv_bfloat16 h2 = __float2bfloat16_rn(f2);
    __nv_bfloat16 h3 = __float2bfloat16_rn(f3);
    __nv_bfloat16 l0 = __float2bfloat16_rn(f0 - __bfloat162float(h0));
    __nv_bfloat16 l1 = __float2bfloat16_rn(f1 - __bfloat162float(h1));
    __nv_bfloat16 l2 = __float2bfloat16_rn(f2 - __bfloat162float(h2));
    __nv_bfloat16 l3 = __float2bfloat16_rn(f3 - __bfloat162float(h3));
    __nv_bfloat162 H0 = __halves2bfloat162(h0, h1);
    __nv_bfloat162 H1 = __halves2bfloat162(h2, h3);
    __nv_bfloat162 L0 = __halves2bfloat162(l0, l1);
    __nv_bfloat162 L1 = __halves2bfloat162(l2, l3);
    *(__nv_bfloat162*)(hi + i)     = H0;
    *(__nv_bfloat162*)(hi + i + 2) = H1;
    *(__nv_bfloat162*)(lo + i)     = L0;
    *(__nv_bfloat162*)(lo + i + 2) = L1;
}

// ---------------------------------------------------------------------------
// bf16x3 GEMM: C[M,N] = A[M,K] @ B[K,N] (row-major, fp32 via split pairs)
// Block 128x128, BK=16, 256 threads (8 warps: 2 M x 4 N), warp tile 64x32.
// ---------------------------------------------------------------------------
#define GBM 128
#define GBN 128
#define GBK 16
#define SA  24    // A smem row stride (bf16): 48B -> conflict-free ldmatrix
#define SB  136   // B smem row stride: 272B -> conflict-free ldmatrix

__global__ __launch_bounds__(256) void gemm_bf16x3(
    const __nv_bfloat16* __restrict__ Ahi, const __nv_bfloat16* __restrict__ Alo,
    const __nv_bfloat16* __restrict__ Bhi, const __nv_bfloat16* __restrict__ Blo,
    float* __restrict__ C, int M, int N, int K)
{
    __shared__ __nv_bfloat16 As[2][2][GBM * SA];   // [stage][hi/lo]
    __shared__ __nv_bfloat16 Bs[2][2][GBK * SB];

    const int tid  = threadIdx.x;
    const int lane = tid & 31;
    const int warp = tid >> 5;
    const int wm   = warp >> 2;    // 0..1
    const int wn   = warp & 3;     // 0..3
    const int bm   = blockIdx.y * GBM;
    const int bn   = blockIdx.x * GBN;

    float acc[4][4][4];
    #pragma unroll
    for (int mi = 0; mi < 4; mi++) {
        #pragma unroll
        for (int ni = 0; ni < 4; ni++) {
            acc[mi][ni][0] = 0.0f;
            acc[mi][ni][1] = 0.0f;
            acc[mi][ni][2] = 0.0f;
            acc[mi][ni][3] = 0.0f;
        }
    }

    // global->smem assignment
    const int a_row = tid >> 1;            // 0..127
    const int a_c   = (tid & 1) * 8;       // 0 or 8 (16B chunks)
    const int b_row = tid >> 4;            // 0..15
    const int b_c   = (tid & 15) * 8;      // 0..120

    const uint32_t sa_hi0 = smem_u32(&As[0][0][a_row * SA + a_c]);
    const uint32_t sa_lo0 = smem_u32(&As[0][1][a_row * SA + a_c]);
    const uint32_t sb_hi0 = smem_u32(&Bs[0][0][b_row * SB + b_c]);
    const uint32_t sb_lo0 = smem_u32(&Bs[0][1][b_row * SB + b_c]);
    const uint32_t a_stage = (uint32_t)(2u * GBM * SA * sizeof(__nv_bfloat16));
    const uint32_t b_stage = (uint32_t)(2u * GBK * SB * sizeof(__nv_bfloat16));

    // prologue: stage 0 loads k0=0
    {
        size_t aoff = (size_t)(bm + a_row) * K + a_c;
        size_t boff = (size_t)b_row * N + bn + b_c;
        cp16(sa_hi0, Ahi + aoff);
        cp16(sa_lo0, Alo + aoff);
        cp16(sb_hi0, Bhi + boff);
        cp16(sb_lo0, Blo + boff);
    }
    cp_commit();

    const int niter = K / GBK;
    for (int it = 0; it < niter; ++it) {
        if (it + 1 < niter) {
            int s = (it + 1) & 1;
            int k0 = (it + 1) * GBK;
            size_t aoff = (size_t)(bm + a_row) * K + k0 + a_c;
            size_t boff = (size_t)(k0 + b_row) * N + bn + b_c;
            cp16(sa_hi0 + s * a_stage, Ahi + aoff);
            cp16(sa_lo0 + s * a_stage, Alo + aoff);
            cp16(sb_hi0 + s * b_stage, Bhi + boff);
            cp16(sb_lo0 + s * b_stage, Blo + boff);
        }
        cp_commit();
        cp_wait1();
        __syncthreads();

        const int s = it & 1;
        uint32_t ah[4][4];
        uint32_t al[4][4];
        uint32_t bh[4][2];
        uint32_t bl[4][2];

        #pragma unroll
        for (int mi = 0; mi < 4; mi++) {
            int r = wm * 64 + mi * 16 + (lane & 15);
            int c = (lane >> 4) * 8;
            ldm_x4(ah[mi], smem_u32(&As[s][0][r * SA + c]));
            ldm_x4(al[mi], smem_u32(&As[s][1][r * SA + c]));
        }
        #pragma unroll
        for (int bi = 0; bi < 2; bi++) {
            int r = lane & 15;
            int c = wn * 32 + bi * 16 + (lane >> 4) * 8;
            uint32_t t0[4];
            uint32_t t1[4];
            ldm_x4_t(t0, smem_u32(&Bs[s][0][r * SB + c]));
            ldm_x4_t(t1, smem_u32(&Bs[s][1][r * SB + c]));
            bh[2 * bi][0]     = t0[0];
            bh[2 * bi][1]     = t0[1];
            bh[2 * bi + 1][0] = t0[2];
            bh[2 * bi + 1][1] = t0[3];
            bl[2 * bi][0]     = t1[0];
            bl[2 * bi][1]     = t1[1];
            bl[2 * bi + 1][0] = t1[2];
            bl[2 * bi + 1][1] = t1[3];
        }

        #pragma unroll
        for (int mi = 0; mi < 4; mi++) {
            #pragma unroll
            for (int ni = 0; ni < 4; ni++) {
                mma16816(acc[mi][ni], ah[mi], bh[ni]);
            }
        }
        #pragma unroll
        for (int mi = 0; mi < 4; mi++) {
            #pragma unroll
            for (int ni = 0; ni < 4; ni++) {
                mma16816(acc[mi][ni], ah[mi], bl[ni]);
            }
        }
        #pragma unroll
        for (int mi = 0; mi < 4; mi++) {
            #pragma unroll
            for (int ni = 0; ni < 4; ni++) {
                mma16816(acc[mi][ni], al[mi], bh[ni]);
            }
        }

        __syncthreads();
    }

    #pragma unroll
    for (int mi = 0; mi < 4; mi++) {
        #pragma unroll
        for (int ni = 0; ni < 4; ni++) {
            int r = bm + wm * 64 + mi * 16 + (lane >> 2);
            int c = bn + wn * 32 + ni * 8 + (lane & 3) * 2;
            float2 v0;
            float2 v1;
            v0.x = acc[mi][ni][0];
            v0.y = acc[mi][ni][1];
            v1.x = acc[mi][ni][2];
            v1.y = acc[mi][ni][3];
            *(float2*)&C[(size_t)r * N + c] = v0;
            *(float2*)&C[(size_t)(r + 8) * N + c] = v1;
        }
    }
}

// ---------------------------------------------------------------------------
// RMSNorm (per head, D=64) + RoPE, in-place on g_qkv. grid=(NQ+NKV, T), blk=64
// ---------------------------------------------------------------------------
__global__ void rmsnorm_rope_kernel(
    float* __restrict__ qkv, const int* __restrict__ positions,
    const float* __restrict__ q_ln_w, const float* __restrict__ k_ln_w)
{
    const int head = blockIdx.x;
    const int t = blockIdx.y;
    const int d = threadIdx.x;

    float* base;
    const float* w;
    if (head < NQ) {
        base = qkv + (size_t)t * QKV_COLS + head * HD;
        w = q_ln_w;
    } else {
        base = qkv + (size_t)t * QKV_COLS + K_OFF + (head - NQ) * HD;
        w = k_ln_w;
    }

    float x = base[d];
    float ss = x * x;
    #pragma unroll
    for (int o = 16; o > 0; o >>= 1) {
        ss += __shfl_xor_sync(0xffffffff, ss, o);
    }

    __shared__ float sred[2];
    if ((d & 31) == 0) { sred[d >> 5] = ss; }
    __syncthreads();
    float sum = sred[0] + sred[1];

    float y = x * rsqrtf(sum * (1.0f / 64.0f) + 1e-5f) * w[d];

    __shared__ float sh[HD];
    sh[d] = y;
    __syncthreads();

    if (d < 32) {
        float x1 = sh[d];
        float x2 = sh[d + 32];
        float pos = (float)positions[t];
        float inv = powf(1000000.0f, -(float)d * (1.0f / 32.0f));
        float s, c;
        sincosf(pos * inv, &s, &c);
        base[d]      = x1 * c - x2 * s;
        base[d + 32] = x2 * c + x1 * s;
    }
}

// ---------------------------------------------------------------------------
// Flash-style causal GQA attention. grid=(T/128, NQ), block=128.
// ---------------------------------------------------------------------------
#define AT_BN 32

__global__ __launch_bounds__(128) void attn_kernel(
    const float* __restrict__ qkv, float* __restrict__ out, int T)
{
    const int qtile = blockIdx.x;
    const int h = blockIdx.y;
    const int kvh = h >> 2;
    const int tid = threadIdx.x;
    const int qi = qtile * 128 + tid;

    float q[HD];
    const float* qptr = qkv + (size_t)qi * QKV_COLS + h * HD;
    #pragma unroll
    for (int d = 0; d < HD; d++) { q[d] = qptr[d]; }

    float o[HD];
    #pragma unroll
    for (int d = 0; d < HD; d++) { o[d] = 0.0f; }
    float m = -1e30f;
    float l = 0.0f;

    __shared__ float Ks[AT_BN][HD];
    __shared__ float Vs[AT_BN][HD];

    const int nk = qtile * 128 + 128;

    for (int k0 = 0; k0 < nk; k0 += AT_BN) {
        __syncthreads();
        #pragma unroll
        for (int r = 0; r < 4; r++) {
            int lin = (r * 128 + tid) * 4;
            int row = lin >> 6;
            int col = lin & 63;
            const float* krow = qkv + (size_t)(k0 + row) * QKV_COLS + K_OFF + kvh * HD + col;
            const float* vrow = qkv + (size_t)(k0 + row) * QKV_COLS + V_OFF + kvh * HD + col;
            *(float4*)&Ks[row][col] = *(const float4*)krow;
            *(float4*)&Vs[row][col] = *(const float4*)vrow;
        }
        __syncthreads();

        float p[AT_BN];
        float mt = m;
        #pragma unroll 4
        for (int j = 0; j < AT_BN; j++) {
            float s0 = 0.f;
            float s1 = 0.f;
            float s2 = 0.f;
            float s3 = 0.f;
            #pragma unroll
            for (int d = 0; d < HD; d += 4) {
                s0 += q[d + 0] * Ks[j][d + 0];
                s1 += q[d + 1] * Ks[j][d + 1];
                s2 += q[d + 2] * Ks[j][d + 2];
                s3 += q[d + 3] * Ks[j][d + 3];
            }
            float s = ((s0 + s1) + (s2 + s3)) * 0.125f;
            if (k0 + j > qi) { s = -1e30f; }
            p[j] = s;
            mt = fmaxf(mt, s);
        }

        float scale = __expf(m - mt);
        l *= scale;
        #pragma unroll
        for (int d = 0; d < HD; d++) { o[d] *= scale; }
        m = mt;

        #pragma unroll 4
        for (int j = 0; j < AT_BN; j++) {
            float pj = __expf(p[j] - mt);
            l += pj;
            #pragma unroll
            for (int d = 0; d < HD; d++) {
                o[d] += pj * Vs[j][d];
            }
        }
    }

    float invl = 1.0f / l;
    float* op = out + (size_t)qi * (NQ * HD) + h * HD;
    #pragma unroll
    for (int d = 0; d < HD; d++) { op[d] = o[d] * invl; }
}

// ---------------------------------------------------------------------------
// Launch
// ---------------------------------------------------------------------------
extern "C" void kernel_launch(void* const* d_in, const int* in_sizes, int n_in,
                              void* d_out, int out_size)
{
    const int*   positions = (const int*)d_in[0];
    const float* hidden    = (const float*)d_in[1];
    const float* w_qkv     = (const float*)d_in[2];
    const float* w_out     = (const float*)d_in[3];
    const float* q_ln_w    = (const float*)d_in[4];
    const float* k_ln_w    = (const float*)d_in[5];
    float* out = (float*)d_out;

    const int T = in_sizes[1] / HID;   // 2048

    float *qkv, *attn;
    __nv_bfloat16 *hid_hi, *hid_lo, *wqkv_hi, *wqkv_lo;
    __nv_bfloat16 *attn_hi, *attn_lo, *wout_hi, *wout_lo;
    cudaGetSymbolAddress((void**)&qkv, g_qkv);
    cudaGetSymbolAddress((void**)&attn, g_attn);
    cudaGetSymbolAddress((void**)&hid_hi, g_hid_hi);
    cudaGetSymbolAddress((void**)&hid_lo, g_hid_lo);
    cudaGetSymbolAddress((void**)&wqkv_hi, g_wqkv_hi);
    cudaGetSymbolAddress((void**)&wqkv_lo, g_wqkv_lo);
    cudaGetSymbolAddress((void**)&attn_hi, g_attn_hi);
    cudaGetSymbolAddress((void**)&attn_lo, g_attn_lo);
    cudaGetSymbolAddress((void**)&wout_hi, g_wout_hi);
    cudaGetSymbolAddress((void**)&wout_lo, g_wout_lo);

    // Split inputs for QKV GEMM
    {
        int n1 = T * HID;
        split_kernel<<<n1 / 1024, 256>>>(hidden, hid_hi, hid_lo, n1);
        int n2 = HID * QKV_COLS;
        split_kernel<<<n2 / 1024, 256>>>(w_qkv, wqkv_hi, wqkv_lo, n2);
    }

    // 1) QKV projection (tensor cores, bf16x3)
    {
        dim3 grid(QKV_COLS / GBN, T / GBM);
        gemm_bf16x3<<<grid, 256>>>(hid_hi, hid_lo, wqkv_hi, wqkv_lo, qkv, T, QKV_COLS, HID);
    }

    // 2) RMSNorm + RoPE
    {
        dim3 grid(NQ + NKV, T);
        rmsnorm_rope_kernel<<<grid, 64>>>(qkv, positions, q_ln_w, k_ln_w);
    }

    // 3) Causal GQA attention
    {
        dim3 grid(T / 128, NQ);
        attn_kernel<<<grid, 128>>>(qkv, attn, T);
    }

    // Split attention output + w_out
    {
        int n1 = T * NQ * HD;
        split_kernel<<<n1 / 1024, 256>>>(attn, attn_hi, attn_lo, n1);
        int n2 = NQ * HD * HID;
        split_kernel<<<n2 / 1024, 256>>>(w_out, wout_hi, wout_lo, n2);
    }

    // 4) Output projection (tensor cores, bf16x3)
    {
        dim3 grid(HID / GBN, T / GBM);
        gemm_bf16x3<<<grid, 256>>>(attn_hi, attn_lo, wout_hi, wout_lo, out, T, HID, NQ * HD);
    }
}

// round 4
// speedup vs baseline: 3.0079x; 1.9656x over previous
#include <cuda_runtime.h>
#include <cuda_bf16.h>
#include <math.h>
#include <stdint.h>

// Problem constants (fixed shapes per reference)
#define T_MAX 2048
#define HID   2048
#define NQ    32
#define NKV   8
#define HD    64
#define QKV_COLS ((NQ + 2*NKV) * HD)   // 3072
#define K_OFF (NQ * HD)                // 2048
#define V_OFF ((NQ + NKV) * HD)        // 2560

// Scratch (no allocation allowed)
__device__ float g_qkv[T_MAX * QKV_COLS];

__device__ __nv_bfloat16 g_hid_hi[T_MAX * HID];
__device__ __nv_bfloat16 g_hid_lo[T_MAX * HID];
__device__ __nv_bfloat16 g_wqkv_hi[HID * QKV_COLS];
__device__ __nv_bfloat16 g_wqkv_lo[HID * QKV_COLS];
__device__ __nv_bfloat16 g_attn_hi[T_MAX * NQ * HD];
__device__ __nv_bfloat16 g_attn_lo[T_MAX * NQ * HD];
__device__ __nv_bfloat16 g_wout_hi[NQ * HD * HID];
__device__ __nv_bfloat16 g_wout_lo[NQ * HD * HID];

__device__ __nv_bfloat16 g_q_hi[T_MAX * NQ * HD];
__device__ __nv_bfloat16 g_q_lo[T_MAX * NQ * HD];
__device__ __nv_bfloat16 g_k_hi[T_MAX * NKV * HD];
__device__ __nv_bfloat16 g_k_lo[T_MAX * NKV * HD];
__device__ __nv_bfloat16 g_v_hi[T_MAX * NKV * HD];
__device__ __nv_bfloat16 g_v_lo[T_MAX * NKV * HD];

// ---------------------------------------------------------------------------
// PTX helpers
// ---------------------------------------------------------------------------
__device__ __forceinline__ void cp16(uint32_t dst, const void* src) {
    asm volatile("cp.async.cg.shared.global [%0], [%1], 16;" :: "r"(dst), "l"(src));
}
__device__ __forceinline__ void cp_commit() {
    asm volatile("cp.async.commit_group;");
}
__device__ __forceinline__ void cp_wait1() {
    asm volatile("cp.async.wait_group 1;");
}
__device__ __forceinline__ void ldm_x4(uint32_t* r, uint32_t a) {
    asm volatile("ldmatrix.sync.aligned.m8n8.x4.shared.b16 {%0,%1,%2,%3}, [%4];"
        : "=r"(r[0]), "=r"(r[1]), "=r"(r[2]), "=r"(r[3]) : "r"(a));
}
__device__ __forceinline__ void ldm_x4_t(uint32_t* r, uint32_t a) {
    asm volatile("ldmatrix.sync.aligned.m8n8.x4.trans.shared.b16 {%0,%1,%2,%3}, [%4];"
        : "=r"(r[0]), "=r"(r[1]), "=r"(r[2]), "=r"(r[3]) : "r"(a));
}
__device__ __forceinline__ void mma16816(float* c, const uint32_t* a, const uint32_t* b) {
    asm volatile(
        "mma.sync.aligned.m16n8k16.row.col.f32.bf16.bf16.f32 "
        "{%0,%1,%2,%3}, {%4,%5,%6,%7}, {%8,%9}, {%0,%1,%2,%3};"
        : "+f"(c[0]), "+f"(c[1]), "+f"(c[2]), "+f"(c[3])
        : "r"(a[0]), "r"(a[1]), "r"(a[2]), "r"(a[3]), "r"(b[0]), "r"(b[1]));
}
__device__ __forceinline__ uint32_t smem_u32(const void* p) {
    return (uint32_t)__cvta_generic_to_shared(p);
}
__device__ __forceinline__ uint32_t pack_bf2(__nv_bfloat16 lo, __nv_bfloat16 hi) {
    __nv_bfloat162 v = __halves2bfloat162(lo, hi);
    return *(uint32_t*)&v;
}

// ---------------------------------------------------------------------------
// Split fp32 -> (hi, lo) bf16 pair
// ---------------------------------------------------------------------------
__global__ __launch_bounds__(256) void split_kernel(
    const float* __restrict__ x, __nv_bfloat16* __restrict__ hi,
    __nv_bfloat16* __restrict__ lo, int n)
{
    int i = (blockIdx.x * 256 + threadIdx.x) * 4;
    if (i >= n) { return; }
    float4 v = *(const float4*)(x + i);
    __nv_bfloat16 h0 = __float2bfloat16_rn(v.x);
    __nv_bfloat16 h1 = __float2bfloat16_rn(v.y);
    __nv_bfloat16 h2 = __float2bfloat16_rn(v.z);
    __nv_bfloat16 h3 = __float2bfloat16_rn(v.w);
    __nv_bfloat16 l0 = __float2bfloat16_rn(v.x - __bfloat162float(h0));
    __nv_bfloat16 l1 = __float2bfloat16_rn(v.y - __bfloat162float(h1));
    __nv_bfloat16 l2 = __float2bfloat16_rn(v.z - __bfloat162float(h2));
    __nv_bfloat16 l3 = __float2bfloat16_rn(v.w - __bfloat162float(h3));
    *(__nv_bfloat162*)(hi + i)     = __halves2bfloat162(h0, h1);
    *(__nv_bfloat162*)(hi + i + 2) = __halves2bfloat162(h2, h3);
    *(__nv_bfloat162*)(lo + i)     = __halves2bfloat162(l0, l1);
    *(__nv_bfloat162*)(lo + i + 2) = __halves2bfloat162(l2, l3);
}

// ---------------------------------------------------------------------------
// bf16x3 GEMM (verified in R3): C[M,N] = A[M,K] @ B[K,N]
// ---------------------------------------------------------------------------
#define GBM 128
#define GBN 128
#define GBK 16
#define SA  24
#define SB  136

__global__ __launch_bounds__(256) void gemm_bf16x3(
    const __nv_bfloat16* __restrict__ Ahi, const __nv_bfloat16* __restrict__ Alo,
    const __nv_bfloat16* __restrict__ Bhi, const __nv_bfloat16* __restrict__ Blo,
    float* __restrict__ C, int M, int N, int K)
{
    __shared__ __nv_bfloat16 As[2][2][GBM * SA];
    __shared__ __nv_bfloat16 Bs[2][2][GBK * SB];

    const int tid  = threadIdx.x;
    const int lane = tid & 31;
    const int warp = tid >> 5;
    const int wm   = warp >> 2;
    const int wn   = warp & 3;
    const int bm   = blockIdx.y * GBM;
    const int bn   = blockIdx.x * GBN;

    float acc[4][4][4];
    #pragma unroll
    for (int mi = 0; mi < 4; mi++) {
        #pragma unroll
        for (int ni = 0; ni < 4; ni++) {
            acc[mi][ni][0] = 0.0f;
            acc[mi][ni][1] = 0.0f;
            acc[mi][ni][2] = 0.0f;
            acc[mi][ni][3] = 0.0f;
        }
    }

    const int a_row = tid >> 1;
    const int a_c   = (tid & 1) * 8;
    const int b_row = tid >> 4;
    const int b_c   = (tid & 15) * 8;

    const uint32_t sa_hi0 = smem_u32(&As[0][0][a_row * SA + a_c]);
    const uint32_t sa_lo0 = smem_u32(&As[0][1][a_row * SA + a_c]);
    const uint32_t sb_hi0 = smem_u32(&Bs[0][0][b_row * SB + b_c]);
    const uint32_t sb_lo0 = smem_u32(&Bs[0][1][b_row * SB + b_c]);
    const uint32_t a_stage = (uint32_t)(2u * GBM * SA * sizeof(__nv_bfloat16));
    const uint32_t b_stage = (uint32_t)(2u * GBK * SB * sizeof(__nv_bfloat16));

    {
        size_t aoff = (size_t)(bm + a_row) * K + a_c;
        size_t boff = (size_t)b_row * N + bn + b_c;
        cp16(sa_hi0, Ahi + aoff);
        cp16(sa_lo0, Alo + aoff);
        cp16(sb_hi0, Bhi + boff);
        cp16(sb_lo0, Blo + boff);
    }
    cp_commit();

    const int niter = K / GBK;
    for (int it = 0; it < niter; ++it) {
        if (it + 1 < niter) {
            int s = (it + 1) & 1;
            int k0 = (it + 1) * GBK;
            size_t aoff = (size_t)(bm + a_row) * K + k0 + a_c;
            size_t boff = (size_t)(k0 + b_row) * N + bn + b_c;
            cp16(sa_hi0 + s * a_stage, Ahi + aoff);
            cp16(sa_lo0 + s * a_stage, Alo + aoff);
            cp16(sb_hi0 + s * b_stage, Bhi + boff);
            cp16(sb_lo0 + s * b_stage, Blo + boff);
        }
        cp_commit();
        cp_wait1();
        __syncthreads();

        const int s = it & 1;
        uint32_t ah[4][4];
        uint32_t al[4][4];
        uint32_t bh[4][2];
        uint32_t bl[4][2];

        #pragma unroll
        for (int mi = 0; mi < 4; mi++) {
            int r = wm * 64 + mi * 16 + (lane & 15);
            int c = (lane >> 4) * 8;
            ldm_x4(ah[mi], smem_u32(&As[s][0][r * SA + c]));
            ldm_x4(al[mi], smem_u32(&As[s][1][r * SA + c]));
        }
        #pragma unroll
        for (int bi = 0; bi < 2; bi++) {
            int r = lane & 15;
            int c = wn * 32 + bi * 16 + (lane >> 4) * 8;
            uint32_t t0[4];
            uint32_t t1[4];
            ldm_x4_t(t0, smem_u32(&Bs[s][0][r * SB + c]));
            ldm_x4_t(t1, smem_u32(&Bs[s][1][r * SB + c]));
            bh[2 * bi][0]     = t0[0];
            bh[2 * bi][1]     = t0[1];
            bh[2 * bi + 1][0] = t0[2];
            bh[2 * bi + 1][1] = t0[3];
            bl[2 * bi][0]     = t1[0];
            bl[2 * bi][1]     = t1[1];
            bl[2 * bi + 1][0] = t1[2];
            bl[2 * bi + 1][1] = t1[3];
        }

        #pragma unroll
        for (int mi = 0; mi < 4; mi++) {
            #pragma unroll
            for (int ni = 0; ni < 4; ni++) {
                mma16816(acc[mi][ni], ah[mi], bh[ni]);
            }
        }
        #pragma unroll
        for (int mi = 0; mi < 4; mi++) {
            #pragma unroll
            for (int ni = 0; ni < 4; ni++) {
                mma16816(acc[mi][ni], ah[mi], bl[ni]);
            }
        }
        #pragma unroll
        for (int mi = 0; mi < 4; mi++) {
            #pragma unroll
            for (int ni = 0; ni < 4; ni++) {
                mma16816(acc[mi][ni], al[mi], bh[ni]);
            }
        }

        __syncthreads();
    }

    #pragma unroll
    for (int mi = 0; mi < 4; mi++) {
        #pragma unroll
        for (int ni = 0; ni < 4; ni++) {
            int r = bm + wm * 64 + mi * 16 + (lane >> 2);
            int c = bn + wn * 32 + ni * 8 + (lane & 3) * 2;
            float2 v0;
            float2 v1;
            v0.x = acc[mi][ni][0];
            v0.y = acc[mi][ni][1];
            v1.x = acc[mi][ni][2];
            v1.y = acc[mi][ni][3];
            *(float2*)&C[(size_t)r * N + c] = v0;
            *(float2*)&C[(size_t)(r + 8) * N + c] = v1;
        }
    }
}

// ---------------------------------------------------------------------------
// RMSNorm + RoPE + split to bf16 hi/lo. grid=(NQ+2*NKV, T), block=64.
// Q heads get the 1/8 score scale folded in. V heads: plain split.
// ---------------------------------------------------------------------------
__global__ void norm_rope_split_kernel(
    const float* __restrict__ qkv, const int* __restrict__ positions,
    const float* __restrict__ q_ln_w, const float* __restrict__ k_ln_w,
    __nv_bfloat16* __restrict__ qhi, __nv_bfloat16* __restrict__ qlo,
    __nv_bfloat16* __restrict__ khi, __nv_bfloat16* __restrict__ klo,
    __nv_bfloat16* __restrict__ vhi, __nv_bfloat16* __restrict__ vlo)
{
    const int head = blockIdx.x;
    const int t = blockIdx.y;
    const int d = threadIdx.x;

    if (head >= NQ + NKV) {
        // V: plain split
        int vh = head - NQ - NKV;
        float x = qkv[(size_t)t * QKV_COLS + V_OFF + vh * HD + d];
        __nv_bfloat16 h = __float2bfloat16_rn(x);
        __nv_bfloat16 l = __float2bfloat16_rn(x - __bfloat162float(h));
        size_t o = (size_t)t * (NKV * HD) + vh * HD + d;
        vhi[o] = h;
        vlo[o] = l;
        return;
    }

    const bool isq = (head < NQ);
    const float* base = qkv + (size_t)t * QKV_COLS +
                        (isq ? head * HD : K_OFF + (head - NQ) * HD);
    const float* w = isq ? q_ln_w : k_ln_w;

    float x = base[d];
    float ss = x * x;
    #pragma unroll
    for (int o = 16; o > 0; o >>= 1) {
        ss += __shfl_xor_sync(0xffffffff, ss, o);
    }

    __shared__ float sred[2];
    if ((d & 31) == 0) { sred[d >> 5] = ss; }
    __syncthreads();
    float sum = sred[0] + sred[1];

    float y = x * rsqrtf(sum * (1.0f / 64.0f) + 1e-5f) * w[d];

    __shared__ float sh[HD];
    sh[d] = y;
    __syncthreads();

    int i = d & 31;
    float pos = (float)positions[t];
    float inv = powf(1000000.0f, -(float)i * (1.0f / 32.0f));
    float s, c;
    sincosf(pos * inv, &s, &c);
    float val;
    if (d < 32) {
        val = sh[d] * c - sh[d + 32] * s;
    } else {
        val = sh[d] * c + sh[d - 32] * s;
    }
    if (isq) { val *= 0.125f; }   // D^-1/2

    __nv_bfloat16 h = __float2bfloat16_rn(val);
    __nv_bfloat16 l = __float2bfloat16_rn(val - __bfloat162float(h));
    if (isq) {
        size_t o = (size_t)t * (NQ * HD) + head * HD + d;
        qhi[o] = h;
        qlo[o] = l;
    } else {
        size_t o = (size_t)t * (NKV * HD) + (head - NQ) * HD + d;
        khi[o] = h;
        klo[o] = l;
    }
}

// ---------------------------------------------------------------------------
// Tensor-core causal flash attention (bf16x3).
// grid = (T/64, NQ), 128 threads (4 warps, m16 each). KV tiles of 64.
// ---------------------------------------------------------------------------
#define AST 72   // smem row stride in bf16 (144B, conflict-free ldmatrix)
#define A_Q_ELEMS (2 * 64 * AST)           // Q hi+lo
#define A_KV_ELEMS (2 * 2 * 64 * AST)      // 2 stages x hi/lo
#define A_SMEM_BYTES ((A_Q_ELEMS + 2 * A_KV_ELEMS) * 2)

__global__ __launch_bounds__(128) void attn_mma_kernel(
    const __nv_bfloat16* __restrict__ qhi, const __nv_bfloat16* __restrict__ qlo,
    const __nv_bfloat16* __restrict__ khi, const __nv_bfloat16* __restrict__ klo,
    const __nv_bfloat16* __restrict__ vhi, const __nv_bfloat16* __restrict__ vlo,
    __nv_bfloat16* __restrict__ ohi, __nv_bfloat16* __restrict__ olo)
{
    extern __shared__ __nv_bfloat16 sm[];
    __nv_bfloat16* Qs  = sm;                       // [hi/lo][64*AST]
    __nv_bfloat16* Ksm = sm + A_Q_ELEMS;           // [stage][hi/lo][64*AST]
    __nv_bfloat16* Vsm = Ksm + 2 * 2 * 64 * AST;

    const int tid  = threadIdx.x;
    const int lane = tid & 31;
    const int warp = tid >> 5;
    const int qtile = blockIdx.x;
    const int h    = blockIdx.y;
    const int kvh  = h >> 2;
    const int qbase = qtile * 64;

    // ---- prologue loads: Q tile + KV stage 0, one cp.async group ----
    #pragma unroll
    for (int i = 0; i < 4; i++) {
        int lin = i * 128 + tid;
        int row = lin >> 3;
        int c = (lin & 7) * 8;
        size_t g = (size_t)(qbase + row) * (NQ * HD) + h * HD + c;
        cp16(smem_u32(Qs + row * AST + c), qhi + g);
        cp16(smem_u32(Qs + 64 * AST + row * AST + c), qlo + g);
        size_t gk = (size_t)row * (NKV * HD) + kvh * HD + c;
        cp16(smem_u32(Ksm + row * AST + c), khi + gk);
        cp16(smem_u32(Ksm + 64 * AST + row * AST + c), klo + gk);
        cp16(smem_u32(Vsm + row * AST + c), vhi + gk);
        cp16(smem_u32(Vsm + 64 * AST + row * AST + c), vlo + gk);
    }
    cp_commit();

    float oacc[8][4];
    #pragma unroll
    for (int ni = 0; ni < 8; ni++) {
        oacc[ni][0] = 0.0f; oacc[ni][1] = 0.0f;
        oacc[ni][2] = 0.0f; oacc[ni][3] = 0.0f;
    }
    float m0 = -1e30f, m1 = -1e30f, l0 = 0.0f, l1 = 0.0f;
    uint32_t aqh[4][4];
    uint32_t aql[4][4];

    const int ntiles = qtile + 1;
    for (int it = 0; it < ntiles; it++) {
        if (it + 1 < ntiles) {
            int s = (it + 1) & 1;
            int k0n = (it + 1) * 64;
            __nv_bfloat16* kb = Ksm + s * (2 * 64 * AST);
            __nv_bfloat16* vb = Vsm + s * (2 * 64 * AST);
            #pragma unroll
            for (int i = 0; i < 4; i++) {
                int lin = i * 128 + tid;
                int row = lin >> 3;
                int c = (lin & 7) * 8;
                size_t g = (size_t)(k0n + row) * (NKV * HD) + kvh * HD + c;
                cp16(smem_u32(kb + row * AST + c), khi + g);
                cp16(smem_u32(kb + 64 * AST + row * AST + c), klo + g);
                cp16(smem_u32(vb + row * AST + c), vhi + g);
                cp16(smem_u32(vb + 64 * AST + row * AST + c), vlo + g);
            }
        }
        cp_commit();
        cp_wait1();
        __syncthreads();

        if (it == 0) {
            // Q a-fragments, once
            #pragma unroll
            for (int ks = 0; ks < 4; ks++) {
                int r = warp * 16 + (lane & 15);
                int c = ks * 16 + (lane >> 4) * 8;
                ldm_x4(aqh[ks], smem_u32(Qs + r * AST + c));
                ldm_x4(aql[ks], smem_u32(Qs + 64 * AST + r * AST + c));
            }
        }

        const int s = it & 1;
        __nv_bfloat16* kb = Ksm + s * (2 * 64 * AST);
        __nv_bfloat16* vb = Vsm + s * (2 * 64 * AST);
        const int k0 = it * 64;

        // ---- S = Q K^T ----
        float sacc[8][4];
        #pragma unroll
        for (int ni = 0; ni < 8; ni++) {
            sacc[ni][0] = 0.0f; sacc[ni][1] = 0.0f;
            sacc[ni][2] = 0.0f; sacc[ni][3] = 0.0f;
        }

        const int krow = ((lane >> 4) << 3) + (lane & 7);
        #pragma unroll
        for (int ks = 0; ks < 4; ks++) {
            int kcol = ks * 16 + ((lane >> 3) & 1) * 8;
            #pragma unroll
            for (int kg = 0; kg < 4; kg++) {
                uint32_t th[4];
                uint32_t tl[4];
                ldm_x4(th, smem_u32(kb + (kg * 16 + krow) * AST + kcol));
                ldm_x4(tl, smem_u32(kb + 64 * AST + (kg * 16 + krow) * AST + kcol));
                uint32_t b0h[2]; b0h[0] = th[0]; b0h[1] = th[1];
                uint32_t b1h[2]; b1h[0] = th[2]; b1h[1] = th[3];
                uint32_t b0l[2]; b0l[0] = tl[0]; b0l[1] = tl[1];
                uint32_t b1l[2]; b1l[0] = tl[2]; b1l[1] = tl[3];
                mma16816(sacc[2 * kg],     aqh[ks], b0h);
                mma16816(sacc[2 * kg + 1], aqh[ks], b1h);
                mma16816(sacc[2 * kg],     aqh[ks], b0l);
                mma16816(sacc[2 * kg + 1], aqh[ks], b1l);
                mma16816(sacc[2 * kg],     aql[ks], b0h);
                mma16816(sacc[2 * kg + 1], aql[ks], b1h);
            }
        }

        // ---- causal mask (only the diagonal tile) ----
        if (k0 + 64 > qbase) {
            int row0 = qbase + warp * 16 + (lane >> 2);
            #pragma unroll
            for (int ni = 0; ni < 8; ni++) {
                int colk = k0 + ni * 8 + (lane & 3) * 2;
                if (colk     > row0)     { sacc[ni][0] = -1e30f; }
                if (colk + 1 > row0)     { sacc[ni][1] = -1e30f; }
                if (colk     > row0 + 8) { sacc[ni][2] = -1e30f; }
                if (colk + 1 > row0 + 8) { sacc[ni][3] = -1e30f; }
            }
        }

        // ---- online softmax ----
        float nm0 = m0;
        float nm1 = m1;
        #pragma unroll
        for (int ni = 0; ni < 8; ni++) {
            nm0 = fmaxf(nm0, fmaxf(sacc[ni][0], sacc[ni][1]));
            nm1 = fmaxf(nm1, fmaxf(sacc[ni][2], sacc[ni][3]));
        }
        nm0 = fmaxf(nm0, __shfl_xor_sync(0xffffffff, nm0, 1));
        nm0 = fmaxf(nm0, __shfl_xor_sync(0xffffffff, nm0, 2));
        nm1 = fmaxf(nm1, __shfl_xor_sync(0xffffffff, nm1, 1));
        nm1 = fmaxf(nm1, __shfl_xor_sync(0xffffffff, nm1, 2));

        float sc0 = __expf(m0 - nm0);
        float sc1 = __expf(m1 - nm1);
        m0 = nm0;
        m1 = nm1;
        l0 *= sc0;
        l1 *= sc1;

        uint32_t phi[8][2];
        uint32_t plo[8][2];
        #pragma unroll
        for (int ni = 0; ni < 8; ni++) {
            float p0 = __expf(sacc[ni][0] - nm0);
            float p1 = __expf(sacc[ni][1] - nm0);
            float p2 = __expf(sacc[ni][2] - nm1);
            float p3 = __expf(sacc[ni][3] - nm1);
            l0 += p0 + p1;
            l1 += p2 + p3;
            __nv_bfloat16 h0 = __float2bfloat16_rn(p0);
            __nv_bfloat16 h1 = __float2bfloat16_rn(p1);
            __nv_bfloat16 h2 = __float2bfloat16_rn(p2);
            __nv_bfloat16 h3 = __float2bfloat16_rn(p3);
            phi[ni][0] = pack_bf2(h0, h1);
            phi[ni][1] = pack_bf2(h2, h3);
            plo[ni][0] = pack_bf2(__float2bfloat16_rn(p0 - __bfloat162float(h0)),
                                  __float2bfloat16_rn(p1 - __bfloat162float(h1)));
            plo[ni][1] = pack_bf2(__float2bfloat16_rn(p2 - __bfloat162float(h2)),
                                  __float2bfloat16_rn(p3 - __bfloat162float(h3)));
            oacc[ni][0] *= sc0;
            oacc[ni][1] *= sc0;
            oacc[ni][2] *= sc1;
            oacc[ni][3] *= sc1;
        }

        // ---- O += P V ----
        #pragma unroll
        for (int ks = 0; ks < 4; ks++) {
            uint32_t aph[4];
            uint32_t apl[4];
            aph[0] = phi[2 * ks][0];     aph[1] = phi[2 * ks][1];
            aph[2] = phi[2 * ks + 1][0]; aph[3] = phi[2 * ks + 1][1];
            apl[0] = plo[2 * ks][0];     apl[1] = plo[2 * ks][1];
            apl[2] = plo[2 * ks + 1][0]; apl[3] = plo[2 * ks + 1][1];
            int vrow = ks * 16 + (lane & 15);
            #pragma unroll
            for (int nd = 0; nd < 4; nd++) {
                int vcol = nd * 16 + (lane >> 4) * 8;
                uint32_t th[4];
                uint32_t tl[4];
                ldm_x4_t(th, smem_u32(vb + vrow * AST + vcol));
                ldm_x4_t(tl, smem_u32(vb + 64 * AST + vrow * AST + vcol));
                uint32_t b0h[2]; b0h[0] = th[0]; b0h[1] = th[1];
                uint32_t b1h[2]; b1h[0] = th[2]; b1h[1] = th[3];
                uint32_t b0l[2]; b0l[0] = tl[0]; b0l[1] = tl[1];
                uint32_t b1l[2]; b1l[0] = tl[2]; b1l[1] = tl[3];
                mma16816(oacc[2 * nd],     aph, b0h);
                mma16816(oacc[2 * nd + 1], aph, b1h);
                mma16816(oacc[2 * nd],     aph, b0l);
                mma16816(oacc[2 * nd + 1], aph, b1l);
                mma16816(oacc[2 * nd],     apl, b0h);
                mma16816(oacc[2 * nd + 1], apl, b1h);
            }
        }

        __syncthreads();   // protect stage before next prefetch overwrites
    }

    // ---- epilogue ----
    l0 += __shfl_xor_sync(0xffffffff, l0, 1);
    l0 += __shfl_xor_sync(0xffffffff, l0, 2);
    l1 += __shfl_xor_sync(0xffffffff, l1, 1);
    l1 += __shfl_xor_sync(0xffffffff, l1, 2);
    float inv0 = 1.0f / l0;
    float inv1 = 1.0f / l1;

    int row0 = qbase + warp * 16 + (lane >> 2);
    #pragma unroll
    for (int ni = 0; ni < 8; ni++) {
        int col = h * HD + ni * 8 + (lane & 3) * 2;
        float f0 = oacc[ni][0] * inv0;
        float f1 = oacc[ni][1] * inv0;
        float f2 = oacc[ni][2] * inv1;
        float f3 = oacc[ni][3] * inv1;
        __nv_bfloat16 h0 = __float2bfloat16_rn(f0);
        __nv_bfloat16 h1 = __float2bfloat16_rn(f1);
        __nv_bfloat16 h2 = __float2bfloat16_rn(f2);
        __nv_bfloat16 h3 = __float2bfloat16_rn(f3);
        __nv_bfloat162 hv0 = __halves2bfloat162(h0, h1);
        __nv_bfloat162 hv1 = __halves2bfloat162(h2, h3);
        __nv_bfloat162 lv0 = __halves2bfloat162(
            __float2bfloat16_rn(f0 - __bfloat162float(h0)),
            __float2bfloat16_rn(f1 - __bfloat162float(h1)));
        __nv_bfloat162 lv1 = __halves2bfloat162(
            __float2bfloat16_rn(f2 - __bfloat162float(h2)),
            __float2bfloat16_rn(f3 - __bfloat162float(h3)));
        *(__nv_bfloat162*)&ohi[(size_t)row0 * (NQ * HD) + col] = hv0;
        *(__nv_bfloat162*)&olo[(size_t)row0 * (NQ * HD) + col] = lv0;
        *(__nv_bfloat162*)&ohi[(size_t)(row0 + 8) * (NQ * HD) + col] = hv1;
        *(__nv_bfloat162*)&olo[(size_t)(row0 + 8) * (NQ * HD) + col] = lv1;
    }
}

// ---------------------------------------------------------------------------
// Launch
// ---------------------------------------------------------------------------
extern "C" void kernel_launch(void* const* d_in, const int* in_sizes, int n_in,
                              void* d_out, int out_size)
{
    const int*   positions = (const int*)d_in[0];
    const float* hidden    = (const float*)d_in[1];
    const float* w_qkv     = (const float*)d_in[2];
    const float* w_out     = (const float*)d_in[3];
    const float* q_ln_w    = (const float*)d_in[4];
    const float* k_ln_w    = (const float*)d_in[5];
    float* out = (float*)d_out;

    const int T = in_sizes[1] / HID;   // 2048

    float* qkv;
    __nv_bfloat16 *hid_hi, *hid_lo, *wqkv_hi, *wqkv_lo;
    __nv_bfloat16 *attn_hi, *attn_lo, *wout_hi, *wout_lo;
    __nv_bfloat16 *q_hi, *q_lo, *k_hi, *k_lo, *v_hi, *v_lo;
    cudaGetSymbolAddress((void**)&qkv, g_qkv);
    cudaGetSymbolAddress((void**)&hid_hi, g_hid_hi);
    cudaGetSymbolAddress((void**)&hid_lo, g_hid_lo);
    cudaGetSymbolAddress((void**)&wqkv_hi, g_wqkv_hi);
    cudaGetSymbolAddress((void**)&wqkv_lo, g_wqkv_lo);
    cudaGetSymbolAddress((void**)&attn_hi, g_attn_hi);
    cudaGetSymbolAddress((void**)&attn_lo, g_attn_lo);
    cudaGetSymbolAddress((void**)&wout_hi, g_wout_hi);
    cudaGetSymbolAddress((void**)&wout_lo, g_wout_lo);
    cudaGetSymbolAddress((void**)&q_hi, g_q_hi);
    cudaGetSymbolAddress((void**)&q_lo, g_q_lo);
    cudaGetSymbolAddress((void**)&k_hi, g_k_hi);
    cudaGetSymbolAddress((void**)&k_lo, g_k_lo);
    cudaGetSymbolAddress((void**)&v_hi, g_v_hi);
    cudaGetSymbolAddress((void**)&v_lo, g_v_lo);

    // Splits for the QKV GEMM inputs
    {
        int n1 = T * HID;
        split_kernel<<<n1 / 1024, 256>>>(hidden, hid_hi, hid_lo, n1);
        int n2 = HID * QKV_COLS;
        split_kernel<<<n2 / 1024, 256>>>(w_qkv, wqkv_hi, wqkv_lo, n2);
        int n3 = NQ * HD * HID;
        split_kernel<<<n3 / 1024, 256>>>(w_out, wout_hi, wout_lo, n3);
    }

    // 1) QKV projection
    {
        dim3 grid(QKV_COLS / GBN, T / GBM);
        gemm_bf16x3<<<grid, 256>>>(hid_hi, hid_lo, wqkv_hi, wqkv_lo, qkv, T, QKV_COLS, HID);
    }

    // 2) RMSNorm + RoPE + split (q scaled by 1/8)
    {
        dim3 grid(NQ + 2 * NKV, T);
        norm_rope_split_kernel<<<grid, 64>>>(qkv, positions, q_ln_w, k_ln_w,
                                             q_hi, q_lo, k_hi, k_lo, v_hi, v_lo);
    }

    // 3) Tensor-core causal attention -> attn hi/lo directly
    {
        cudaFuncSetAttribute(attn_mma_kernel,
                             cudaFuncAttributeMaxDynamicSharedMemorySize, A_SMEM_BYTES);
        dim3 grid(T / 64, NQ);
        attn_mma_kernel<<<grid, 128, A_SMEM_BYTES>>>(q_hi, q_lo, k_hi, k_lo,
                                                     v_hi, v_lo, attn_hi, attn_lo);
    }

    // 4) Output projection
    {
        dim3 grid(HID / GBN, T / GBM);
        gemm_bf16x3<<<grid, 256>>>(attn_hi, attn_lo, wout_hi, wout_lo, out, T, HID, NQ * HD);
    }
}

// round 5
// speedup vs baseline: 3.3263x; 1.1058x over previous
#include <cuda_runtime.h>
#include <cuda_bf16.h>
#include <math.h>
#include <stdint.h>

// Problem constants (fixed shapes per reference)
#define T_MAX 2048
#define HID   2048
#define NQ    32
#define NKV   8
#define HD    64
#define QKV_COLS ((NQ + 2*NKV) * HD)   // 3072
#define K_OFF (NQ * HD)                // 2048
#define V_OFF ((NQ + NKV) * HD)        // 2560

// Scratch (no allocation allowed)
__device__ float g_qkv[T_MAX * QKV_COLS];

__device__ __nv_bfloat16 g_hid_hi[T_MAX * HID];
__device__ __nv_bfloat16 g_hid_lo[T_MAX * HID];
__device__ __nv_bfloat16 g_wqkv_hi[HID * QKV_COLS];
__device__ __nv_bfloat16 g_wqkv_lo[HID * QKV_COLS];
__device__ __nv_bfloat16 g_attn_hi[T_MAX * NQ * HD];
__device__ __nv_bfloat16 g_attn_lo[T_MAX * NQ * HD];
__device__ __nv_bfloat16 g_wout_hi[NQ * HD * HID];
__device__ __nv_bfloat16 g_wout_lo[NQ * HD * HID];

__device__ __nv_bfloat16 g_q_hi[T_MAX * NQ * HD];
__device__ __nv_bfloat16 g_q_lo[T_MAX * NQ * HD];
__device__ __nv_bfloat16 g_k_hi[T_MAX * NKV * HD];
__device__ __nv_bfloat16 g_k_lo[T_MAX * NKV * HD];
__device__ __nv_bfloat16 g_v_hi[T_MAX * NKV * HD];
__device__ __nv_bfloat16 g_v_lo[T_MAX * NKV * HD];

// ---------------------------------------------------------------------------
// PTX helpers
// ---------------------------------------------------------------------------
__device__ __forceinline__ void cp16(uint32_t dst, const void* src) {
    asm volatile("cp.async.cg.shared.global [%0], [%1], 16;" :: "r"(dst), "l"(src));
}
__device__ __forceinline__ void cp_commit() {
    asm volatile("cp.async.commit_group;");
}
__device__ __forceinline__ void cp_wait1() {
    asm volatile("cp.async.wait_group 1;");
}
__device__ __forceinline__ void cp_wait2() {
    asm volatile("cp.async.wait_group 2;");
}
__device__ __forceinline__ void ldm_x4(uint32_t* r, uint32_t a) {
    asm volatile("ldmatrix.sync.aligned.m8n8.x4.shared.b16 {%0,%1,%2,%3}, [%4];"
        : "=r"(r[0]), "=r"(r[1]), "=r"(r[2]), "=r"(r[3]) : "r"(a));
}
__device__ __forceinline__ void ldm_x4_t(uint32_t* r, uint32_t a) {
    asm volatile("ldmatrix.sync.aligned.m8n8.x4.trans.shared.b16 {%0,%1,%2,%3}, [%4];"
        : "=r"(r[0]), "=r"(r[1]), "=r"(r[2]), "=r"(r[3]) : "r"(a));
}
__device__ __forceinline__ void mma16816(float* c, const uint32_t* a, const uint32_t* b) {
    asm volatile(
        "mma.sync.aligned.m16n8k16.row.col.f32.bf16.bf16.f32 "
        "{%0,%1,%2,%3}, {%4,%5,%6,%7}, {%8,%9}, {%0,%1,%2,%3};"
        : "+f"(c[0]), "+f"(c[1]), "+f"(c[2]), "+f"(c[3])
        : "r"(a[0]), "r"(a[1]), "r"(a[2]), "r"(a[3]), "r"(b[0]), "r"(b[1]));
}
__device__ __forceinline__ uint32_t smem_u32(const void* p) {
    return (uint32_t)__cvta_generic_to_shared(p);
}
__device__ __forceinline__ uint32_t pack_bf2(__nv_bfloat16 lo, __nv_bfloat16 hi) {
    __nv_bfloat162 v = __halves2bfloat162(lo, hi);
    return *(uint32_t*)&v;
}

// ---------------------------------------------------------------------------
// Split fp32 -> (hi, lo) bf16 pair
// ---------------------------------------------------------------------------
__global__ __launch_bounds__(256) void split_kernel(
    const float* __restrict__ x, __nv_bfloat16* __restrict__ hi,
    __nv_bfloat16* __restrict__ lo, int n)
{
    int i = (blockIdx.x * 256 + threadIdx.x) * 4;
    if (i >= n) { return; }
    float4 v = *(const float4*)(x + i);
    __nv_bfloat16 h0 = __float2bfloat16_rn(v.x);
    __nv_bfloat16 h1 = __float2bfloat16_rn(v.y);
    __nv_bfloat16 h2 = __float2bfloat16_rn(v.z);
    __nv_bfloat16 h3 = __float2bfloat16_rn(v.w);
    __nv_bfloat16 l0 = __float2bfloat16_rn(v.x - __bfloat162float(h0));
    __nv_bfloat16 l1 = __float2bfloat16_rn(v.y - __bfloat162float(h1));
    __nv_bfloat16 l2 = __float2bfloat16_rn(v.z - __bfloat162float(h2));
    __nv_bfloat16 l3 = __float2bfloat16_rn(v.w - __bfloat162float(h3));
    *(__nv_bfloat162*)(hi + i)     = __halves2bfloat162(h0, h1);
    *(__nv_bfloat162*)(hi + i + 2) = __halves2bfloat162(h2, h3);
    *(__nv_bfloat162*)(lo + i)     = __halves2bfloat162(l0, l1);
    *(__nv_bfloat162*)(lo + i + 2) = __halves2bfloat162(l2, l3);
}

// ---------------------------------------------------------------------------
// bf16x3 GEMM: C[M,N] = A[M,K] @ B[K,N], 4-stage cp.async ring, 1 sync/iter.
// Block 128x128, GBK=16, 256 threads (8 warps: 2M x 4N), warp tile 64x32.
// ---------------------------------------------------------------------------
#define GBM 128
#define GBN 128
#define GBK 16
#define SA  24
#define SB  136
#define A_STAGE (2 * GBM * SA)     // hi+lo elems per stage (6144)
#define B_STAGE (2 * GBK * SB)     // (4352)
#define G_SMEM_BYTES ((4 * A_STAGE + 4 * B_STAGE) * 2)   // 83968

__global__ __launch_bounds__(256, 2) void gemm_bf16x3(
    const __nv_bfloat16* __restrict__ Ahi, const __nv_bfloat16* __restrict__ Alo,
    const __nv_bfloat16* __restrict__ Bhi, const __nv_bfloat16* __restrict__ Blo,
    float* __restrict__ C, int M, int N, int K)
{
    extern __shared__ __nv_bfloat16 sm[];
    __nv_bfloat16* As = sm;                 // [4 stages][hi|lo][128*SA]
    __nv_bfloat16* Bs = sm + 4 * A_STAGE;   // [4 stages][hi|lo][16*SB]

    const int tid  = threadIdx.x;
    const int lane = tid & 31;
    const int warp = tid >> 5;
    const int wm   = warp >> 2;
    const int wn   = warp & 3;
    const int bm   = blockIdx.y * GBM;
    const int bn   = blockIdx.x * GBN;

    float acc[4][4][4];
    #pragma unroll
    for (int mi = 0; mi < 4; mi++) {
        #pragma unroll
        for (int ni = 0; ni < 4; ni++) {
            acc[mi][ni][0] = 0.0f;
            acc[mi][ni][1] = 0.0f;
            acc[mi][ni][2] = 0.0f;
            acc[mi][ni][3] = 0.0f;
        }
    }

    const int a_row = tid >> 1;
    const int a_c   = (tid & 1) * 8;
    const int b_row = tid >> 4;
    const int b_c   = (tid & 15) * 8;

    const int niter = K / GBK;

    // prologue: stages 0,1,2
    #pragma unroll
    for (int p = 0; p < 3; p++) {
        int k0 = p * GBK;
        size_t aoff = (size_t)(bm + a_row) * K + k0 + a_c;
        size_t boff = (size_t)(k0 + b_row) * N + bn + b_c;
        __nv_bfloat16* asb = As + p * A_STAGE;
        __nv_bfloat16* bsb = Bs + p * B_STAGE;
        cp16(smem_u32(asb + a_row * SA + a_c), Ahi + aoff);
        cp16(smem_u32(asb + GBM * SA + a_row * SA + a_c), Alo + aoff);
        cp16(smem_u32(bsb + b_row * SB + b_c), Bhi + boff);
        cp16(smem_u32(bsb + GBK * SB + b_row * SB + b_c), Blo + boff);
        cp_commit();
    }

    for (int it = 0; it < niter; ++it) {
        cp_wait2();
        __syncthreads();

        if (it + 3 < niter) {
            int s = (it + 3) & 3;
            int k0 = (it + 3) * GBK;
            size_t aoff = (size_t)(bm + a_row) * K + k0 + a_c;
            size_t boff = (size_t)(k0 + b_row) * N + bn + b_c;
            __nv_bfloat16* asb = As + s * A_STAGE;
            __nv_bfloat16* bsb = Bs + s * B_STAGE;
            cp16(smem_u32(asb + a_row * SA + a_c), Ahi + aoff);
            cp16(smem_u32(asb + GBM * SA + a_row * SA + a_c), Alo + aoff);
            cp16(smem_u32(bsb + b_row * SB + b_c), Bhi + boff);
            cp16(smem_u32(bsb + GBK * SB + b_row * SB + b_c), Blo + boff);
        }
        cp_commit();

        const int s = it & 3;
        __nv_bfloat16* asb = As + s * A_STAGE;
        __nv_bfloat16* bsb = Bs + s * B_STAGE;

        uint32_t ah[4][4];
        uint32_t al[4][4];
        uint32_t bh[4][2];
        uint32_t bl[4][2];

        #pragma unroll
        for (int mi = 0; mi < 4; mi++) {
            int r = wm * 64 + mi * 16 + (lane & 15);
            int c = (lane >> 4) * 8;
            ldm_x4(ah[mi], smem_u32(asb + r * SA + c));
            ldm_x4(al[mi], smem_u32(asb + GBM * SA + r * SA + c));
        }
        #pragma unroll
        for (int bi = 0; bi < 2; bi++) {
            int r = lane & 15;
            int c = wn * 32 + bi * 16 + (lane >> 4) * 8;
            uint32_t t0[4];
            uint32_t t1[4];
            ldm_x4_t(t0, smem_u32(bsb + r * SB + c));
            ldm_x4_t(t1, smem_u32(bsb + GBK * SB + r * SB + c));
            bh[2 * bi][0]     = t0[0];
            bh[2 * bi][1]     = t0[1];
            bh[2 * bi + 1][0] = t0[2];
            bh[2 * bi + 1][1] = t0[3];
            bl[2 * bi][0]     = t1[0];
            bl[2 * bi][1]     = t1[1];
            bl[2 * bi + 1][0] = t1[2];
            bl[2 * bi + 1][1] = t1[3];
        }

        #pragma unroll
        for (int mi = 0; mi < 4; mi++) {
            #pragma unroll
            for (int ni = 0; ni < 4; ni++) {
                mma16816(acc[mi][ni], ah[mi], bh[ni]);
            }
        }
        #pragma unroll
        for (int mi = 0; mi < 4; mi++) {
            #pragma unroll
            for (int ni = 0; ni < 4; ni++) {
                mma16816(acc[mi][ni], ah[mi], bl[ni]);
            }
        }
        #pragma unroll
        for (int mi = 0; mi < 4; mi++) {
            #pragma unroll
            for (int ni = 0; ni < 4; ni++) {
                mma16816(acc[mi][ni], al[mi], bh[ni]);
            }
        }
    }

    #pragma unroll
    for (int mi = 0; mi < 4; mi++) {
        #pragma unroll
        for (int ni = 0; ni < 4; ni++) {
            int r = bm + wm * 64 + mi * 16 + (lane >> 2);
            int c = bn + wn * 32 + ni * 8 + (lane & 3) * 2;
            float2 v0;
            float2 v1;
            v0.x = acc[mi][ni][0];
            v0.y = acc[mi][ni][1];
            v1.x = acc[mi][ni][2];
            v1.y = acc[mi][ni][3];
            *(float2*)&C[(size_t)r * N + c] = v0;
            *(float2*)&C[(size_t)(r + 8) * N + c] = v1;
        }
    }
}

// ---------------------------------------------------------------------------
// RMSNorm + RoPE + split, one warp per (token, head). Lane owns (d, d+32).
// 256 threads = 8 warps. grid = T*(NQ+2NKV)/8 blocks.
// ---------------------------------------------------------------------------
__global__ __launch_bounds__(256) void norm_rope_split_kernel(
    const float* __restrict__ qkv, const int* __restrict__ positions,
    const float* __restrict__ q_ln_w, const float* __restrict__ k_ln_w,
    __nv_bfloat16* __restrict__ qhi, __nv_bfloat16* __restrict__ qlo,
    __nv_bfloat16* __restrict__ khi, __nv_bfloat16* __restrict__ klo,
    __nv_bfloat16* __restrict__ vhi, __nv_bfloat16* __restrict__ vlo)
{
    const int gw   = blockIdx.x * 8 + (threadIdx.x >> 5);
    const int lane = threadIdx.x & 31;
    const int head = gw % (NQ + 2 * NKV);
    const int t    = gw / (NQ + 2 * NKV);

    if (head >= NQ + NKV) {
        int vh = head - NQ - NKV;
        const float* base = qkv + (size_t)t * QKV_COLS + V_OFF + vh * HD;
        float x1 = base[lane];
        float x2 = base[lane + 32];
        __nv_bfloat16 h1 = __float2bfloat16_rn(x1);
        __nv_bfloat16 h2 = __float2bfloat16_rn(x2);
        size_t o = (size_t)t * (NKV * HD) + vh * HD + lane;
        vhi[o]      = h1;
        vhi[o + 32] = h2;
        vlo[o]      = __float2bfloat16_rn(x1 - __bfloat162float(h1));
        vlo[o + 32] = __float2bfloat16_rn(x2 - __bfloat162float(h2));
        return;
    }

    const bool isq = (head < NQ);
    const float* base = qkv + (size_t)t * QKV_COLS +
                        (isq ? head * HD : K_OFF + (head - NQ) * HD);
    const float* w = isq ? q_ln_w : k_ln_w;

    float x1 = base[lane];
    float x2 = base[lane + 32];
    float ss = x1 * x1 + x2 * x2;
    #pragma unroll
    for (int o = 16; o > 0; o >>= 1) {
        ss += __shfl_xor_sync(0xffffffff, ss, o);
    }
    float rs = rsqrtf(ss * (1.0f / 64.0f) + 1e-5f);
    float y1 = x1 * rs * w[lane];
    float y2 = x2 * rs * w[lane + 32];

    float pos = (float)positions[t];
    float inv = powf(1000000.0f, -(float)lane * (1.0f / 32.0f));
    float s, c;
    sincosf(pos * inv, &s, &c);
    float o1 = y1 * c - y2 * s;
    float o2 = y2 * c + y1 * s;
    if (isq) {
        o1 *= 0.125f;
        o2 *= 0.125f;
    }

    __nv_bfloat16 h1 = __float2bfloat16_rn(o1);
    __nv_bfloat16 h2 = __float2bfloat16_rn(o2);
    __nv_bfloat16 l1 = __float2bfloat16_rn(o1 - __bfloat162float(h1));
    __nv_bfloat16 l2 = __float2bfloat16_rn(o2 - __bfloat162float(h2));
    if (isq) {
        size_t o = (size_t)t * (NQ * HD) + head * HD + lane;
        qhi[o]      = h1;
        qhi[o + 32] = h2;
        qlo[o]      = l1;
        qlo[o + 32] = l2;
    } else {
        size_t o = (size_t)t * (NKV * HD) + (head - NQ) * HD + lane;
        khi[o]      = h1;
        khi[o + 32] = h2;
        klo[o]      = l1;
        klo[o + 32] = l2;
    }
}

// ---------------------------------------------------------------------------
// Tensor-core causal flash attention (bf16x3).
// 256 threads (8 warps), 128 q-rows per block, KV tiles of 64.
// 3 smem regions; Q staging region recycled as KV stage after frag load.
// ---------------------------------------------------------------------------
#define AST 72
#define AREG (4 * 64 * AST)                // region elems (18432)
#define A_SMEM_BYTES (3 * AREG * 2)        // 110592

__global__ __launch_bounds__(256, 2) void attn_mma_kernel(
    const __nv_bfloat16* __restrict__ qhi, const __nv_bfloat16* __restrict__ qlo,
    const __nv_bfloat16* __restrict__ khi, const __nv_bfloat16* __restrict__ klo,
    const __nv_bfloat16* __restrict__ vhi, const __nv_bfloat16* __restrict__ vlo,
    __nv_bfloat16* __restrict__ ohi, __nv_bfloat16* __restrict__ olo)
{
    extern __shared__ __nv_bfloat16 sm[];

    const int tid  = threadIdx.x;
    const int lane = tid & 31;
    const int warp = tid >> 5;
    const int qtile = gridDim.x - 1 - blockIdx.x;   // heavy tiles first
    const int h    = blockIdx.y;
    const int kvh  = h >> 2;
    const int qbase = qtile * 128;
    const int ntiles = 2 * qtile + 2;

    // ---- prologue: Q into region0 + KV tile0 into region1 (group0) ----
    #pragma unroll
    for (int i = 0; i < 4; i++) {
        int lin = i * 256 + tid;
        int row = lin >> 3;
        int c = (lin & 7) * 8;
        size_t g = (size_t)(qbase + row) * (NQ * HD) + h * HD + c;
        cp16(smem_u32(sm + row * AST + c), qhi + g);
        cp16(smem_u32(sm + 128 * AST + row * AST + c), qlo + g);
    }
    {
        __nv_bfloat16* rb = sm + AREG;   // region1 = tile0
        #pragma unroll
        for (int i = 0; i < 2; i++) {
            int lin = i * 256 + tid;
            int row = lin >> 3;
            int c = (lin & 7) * 8;
            size_t g = (size_t)row * (NKV * HD) + kvh * HD + c;
            cp16(smem_u32(rb + row * AST + c), khi + g);
            cp16(smem_u32(rb + 64 * AST + row * AST + c), klo + g);
            cp16(smem_u32(rb + 128 * AST + row * AST + c), vhi + g);
            cp16(smem_u32(rb + 192 * AST + row * AST + c), vlo + g);
        }
    }
    cp_commit();
    // tile1 into region2 (group1)
    if (ntiles > 1) {
        __nv_bfloat16* rb = sm + 2 * AREG;
        #pragma unroll
        for (int i = 0; i < 2; i++) {
            int lin = i * 256 + tid;
            int row = lin >> 3;
            int c = (lin & 7) * 8;
            size_t g = (size_t)(64 + row) * (NKV * HD) + kvh * HD + c;
            cp16(smem_u32(rb + row * AST + c), khi + g);
            cp16(smem_u32(rb + 64 * AST + row * AST + c), klo + g);
            cp16(smem_u32(rb + 128 * AST + row * AST + c), vhi + g);
            cp16(smem_u32(rb + 192 * AST + row * AST + c), vlo + g);
        }
    }
    cp_commit();

    cp_wait1();
    __syncthreads();

    // Q fragments (rows warp*16..+15), then free region0 for KV reuse
    uint32_t aqh[4][4];
    uint32_t aql[4][4];
    #pragma unroll
    for (int ks = 0; ks < 4; ks++) {
        int r = warp * 16 + (lane & 15);
        int c = ks * 16 + (lane >> 4) * 8;
        ldm_x4(aqh[ks], smem_u32(sm + r * AST + c));
        ldm_x4(aql[ks], smem_u32(sm + 128 * AST + r * AST + c));
    }
    __syncthreads();

    float oacc[8][4];
    #pragma unroll
    for (int ni = 0; ni < 8; ni++) {
        oacc[ni][0] = 0.0f; oacc[ni][1] = 0.0f;
        oacc[ni][2] = 0.0f; oacc[ni][3] = 0.0f;
    }
    float m0 = -1e30f, m1 = -1e30f, l0 = 0.0f, l1 = 0.0f;

    const int rowlim = qbase + warp * 16 + 15;   // last row this warp owns

    for (int it = 0; it < ntiles; it++) {
        cp_wait1();
        __syncthreads();

        // prefetch tile it+2 into region ((it+3)%3)
        if (it + 2 < ntiles) {
            __nv_bfloat16* rb = sm + ((it + 3) % 3) * AREG;
            int k0n = (it + 2) * 64;
            #pragma unroll
            for (int i = 0; i < 2; i++) {
                int lin = i * 256 + tid;
                int row = lin >> 3;
                int c = (lin & 7) * 8;
                size_t g = (size_t)(k0n + row) * (NKV * HD) + kvh * HD + c;
                cp16(smem_u32(rb + row * AST + c), khi + g);
                cp16(smem_u32(rb + 64 * AST + row * AST + c), klo + g);
                cp16(smem_u32(rb + 128 * AST + row * AST + c), vhi + g);
                cp16(smem_u32(rb + 192 * AST + row * AST + c), vlo + g);
            }
        }
        cp_commit();

        const int k0 = it * 64;
        if (k0 > rowlim) { continue; }   // fully above diagonal for this warp

        __nv_bfloat16* rb = sm + ((it + 1) % 3) * AREG;
        __nv_bfloat16* kbh = rb;
        __nv_bfloat16* kbl = rb + 64 * AST;
        __nv_bfloat16* vbh = rb + 128 * AST;
        __nv_bfloat16* vbl = rb + 192 * AST;

        // ---- S = Q K^T ----
        float sacc[8][4];
        #pragma unroll
        for (int ni = 0; ni < 8; ni++) {
            sacc[ni][0] = 0.0f; sacc[ni][1] = 0.0f;
            sacc[ni][2] = 0.0f; sacc[ni][3] = 0.0f;
        }

        const int krow = ((lane >> 4) << 3) + (lane & 7);
        #pragma unroll
        for (int ks = 0; ks < 4; ks++) {
            int kcol = ks * 16 + ((lane >> 3) & 1) * 8;
            #pragma unroll
            for (int kg = 0; kg < 4; kg++) {
                uint32_t th[4];
                uint32_t tl[4];
                ldm_x4(th, smem_u32(kbh + (kg * 16 + krow) * AST + kcol));
                ldm_x4(tl, smem_u32(kbl + (kg * 16 + krow) * AST + kcol));
                uint32_t b0h[2]; b0h[0] = th[0]; b0h[1] = th[1];
                uint32_t b1h[2]; b1h[0] = th[2]; b1h[1] = th[3];
                uint32_t b0l[2]; b0l[0] = tl[0]; b0l[1] = tl[1];
                uint32_t b1l[2]; b1l[0] = tl[2]; b1l[1] = tl[3];
                mma16816(sacc[2 * kg],     aqh[ks], b0h);
                mma16816(sacc[2 * kg + 1], aqh[ks], b1h);
                mma16816(sacc[2 * kg],     aqh[ks], b0l);
                mma16816(sacc[2 * kg + 1], aqh[ks], b1l);
                mma16816(sacc[2 * kg],     aql[ks], b0h);
                mma16816(sacc[2 * kg + 1], aql[ks], b1h);
            }
        }

        // ---- causal mask (tiles overlapping this warp's rows) ----
        if (k0 + 64 > qbase + warp * 16) {
            int row0 = qbase + warp * 16 + (lane >> 2);
            #pragma unroll
            for (int ni = 0; ni < 8; ni++) {
                int colk = k0 + ni * 8 + (lane & 3) * 2;
                if (colk     > row0)     { sacc[ni][0] = -1e30f; }
                if (colk + 1 > row0)     { sacc[ni][1] = -1e30f; }
                if (colk     > row0 + 8) { sacc[ni][2] = -1e30f; }
                if (colk + 1 > row0 + 8) { sacc[ni][3] = -1e30f; }
            }
        }

        // ---- online softmax ----
        float nm0 = m0;
        float nm1 = m1;
        #pragma unroll
        for (int ni = 0; ni < 8; ni++) {
            nm0 = fmaxf(nm0, fmaxf(sacc[ni][0], sacc[ni][1]));
            nm1 = fmaxf(nm1, fmaxf(sacc[ni][2], sacc[ni][3]));
        }
        nm0 = fmaxf(nm0, __shfl_xor_sync(0xffffffff, nm0, 1));
        nm0 = fmaxf(nm0, __shfl_xor_sync(0xffffffff, nm0, 2));
        nm1 = fmaxf(nm1, __shfl_xor_sync(0xffffffff, nm1, 1));
        nm1 = fmaxf(nm1, __shfl_xor_sync(0xffffffff, nm1, 2));

        float sc0 = __expf(m0 - nm0);
        float sc1 = __expf(m1 - nm1);
        m0 = nm0;
        m1 = nm1;
        l0 *= sc0;
        l1 *= sc1;

        uint32_t phi[8][2];
        uint32_t plo[8][2];
        #pragma unroll
        for (int ni = 0; ni < 8; ni++) {
            float p0 = __expf(sacc[ni][0] - nm0);
            float p1 = __expf(sacc[ni][1] - nm0);
            float p2 = __expf(sacc[ni][2] - nm1);
            float p3 = __expf(sacc[ni][3] - nm1);
            l0 += p0 + p1;
            l1 += p2 + p3;
            __nv_bfloat16 h0 = __float2bfloat16_rn(p0);
            __nv_bfloat16 h1 = __float2bfloat16_rn(p1);
            __nv_bfloat16 h2 = __float2bfloat16_rn(p2);
            __nv_bfloat16 h3 = __float2bfloat16_rn(p3);
            phi[ni][0] = pack_bf2(h0, h1);
            phi[ni][1] = pack_bf2(h2, h3);
            plo[ni][0] = pack_bf2(__float2bfloat16_rn(p0 - __bfloat162float(h0)),
                                  __float2bfloat16_rn(p1 - __bfloat162float(h1)));
            plo[ni][1] = pack_bf2(__float2bfloat16_rn(p2 - __bfloat162float(h2)),
                                  __float2bfloat16_rn(p3 - __bfloat162float(h3)));
            oacc[ni][0] *= sc0;
            oacc[ni][1] *= sc0;
            oacc[ni][2] *= sc1;
            oacc[ni][3] *= sc1;
        }

        // ---- O += P V ----
        #pragma unroll
        for (int ks = 0; ks < 4; ks++) {
            uint32_t aph[4];
            uint32_t apl[4];
            aph[0] = phi[2 * ks][0];     aph[1] = phi[2 * ks][1];
            aph[2] = phi[2 * ks + 1][0]; aph[3] = phi[2 * ks + 1][1];
            apl[0] = plo[2 * ks][0];     apl[1] = plo[2 * ks][1];
            apl[2] = plo[2 * ks + 1][0]; apl[3] = plo[2 * ks + 1][1];
            int vrow = ks * 16 + (lane & 15);
            #pragma unroll
            for (int nd = 0; nd < 4; nd++) {
                int vcol = nd * 16 + (lane >> 4) * 8;
                uint32_t th[4];
                uint32_t tl[4];
                ldm_x4_t(th, smem_u32(vbh + vrow * AST + vcol));
                ldm_x4_t(tl, smem_u32(vbl + vrow * AST + vcol));
                uint32_t b0h[2]; b0h[0] = th[0]; b0h[1] = th[1];
                uint32_t b1h[2]; b1h[0] = th[2]; b1h[1] = th[3];
                uint32_t b0l[2]; b0l[0] = tl[0]; b0l[1] = tl[1];
                uint32_t b1l[2]; b1l[0] = tl[2]; b1l[1] = tl[3];
                mma16816(oacc[2 * nd],     aph, b0h);
                mma16816(oacc[2 * nd + 1], aph, b1h);
                mma16816(oacc[2 * nd],     aph, b0l);
                mma16816(oacc[2 * nd + 1], aph, b1l);
                mma16816(oacc[2 * nd],     apl, b0h);
                mma16816(oacc[2 * nd + 1], apl, b1h);
            }
        }
    }

    // ---- epilogue ----
    l0 += __shfl_xor_sync(0xffffffff, l0, 1);
    l0 += __shfl_xor_sync(0xffffffff, l0, 2);
    l1 += __shfl_xor_sync(0xffffffff, l1, 1);
    l1 += __shfl_xor_sync(0xffffffff, l1, 2);
    float inv0 = 1.0f / l0;
    float inv1 = 1.0f / l1;

    int row0 = qbase + warp * 16 + (lane >> 2);
    #pragma unroll
    for (int ni = 0; ni < 8; ni++) {
        int col = h * HD + ni * 8 + (lane & 3) * 2;
        float f0 = oacc[ni][0] * inv0;
        float f1 = oacc[ni][1] * inv0;
        float f2 = oacc[ni][2] * inv1;
        float f3 = oacc[ni][3] * inv1;
        __nv_bfloat16 h0 = __float2bfloat16_rn(f0);
        __nv_bfloat16 h1 = __float2bfloat16_rn(f1);
        __nv_bfloat16 h2 = __float2bfloat16_rn(f2);
        __nv_bfloat16 h3 = __float2bfloat16_rn(f3);
        __nv_bfloat162 hv0 = __halves2bfloat162(h0, h1);
        __nv_bfloat162 hv1 = __halves2bfloat162(h2, h3);
        __nv_bfloat162 lv0 = __halves2bfloat162(
            __float2bfloat16_rn(f0 - __bfloat162float(h0)),
            __float2bfloat16_rn(f1 - __bfloat162float(h1)));
        __nv_bfloat162 lv1 = __halves2bfloat162(
            __float2bfloat16_rn(f2 - __bfloat162float(h2)),
            __float2bfloat16_rn(f3 - __bfloat162float(h3)));
        *(__nv_bfloat162*)&ohi[(size_t)row0 * (NQ * HD) + col] = hv0;
        *(__nv_bfloat162*)&olo[(size_t)row0 * (NQ * HD) + col] = lv0;
        *(__nv_bfloat162*)&ohi[(size_t)(row0 + 8) * (NQ * HD) + col] = hv1;
        *(__nv_bfloat162*)&olo[(size_t)(row0 + 8) * (NQ * HD) + col] = lv1;
    }
}

// ---------------------------------------------------------------------------
// Launch
// ---------------------------------------------------------------------------
extern "C" void kernel_launch(void* const* d_in, const int* in_sizes, int n_in,
                              void* d_out, int out_size)
{
    const int*   positions = (const int*)d_in[0];
    const float* hidden    = (const float*)d_in[1];
    const float* w_qkv     = (const float*)d_in[2];
    const float* w_out     = (const float*)d_in[3];
    const float* q_ln_w    = (const float*)d_in[4];
    const float* k_ln_w    = (const float*)d_in[5];
    float* out = (float*)d_out;

    const int T = in_sizes[1] / HID;   // 2048

    float* qkv;
    __nv_bfloat16 *hid_hi, *hid_lo, *wqkv_hi, *wqkv_lo;
    __nv_bfloat16 *attn_hi, *attn_lo, *wout_hi, *wout_lo;
    __nv_bfloat16 *q_hi, *q_lo, *k_hi, *k_lo, *v_hi, *v_lo;
    cudaGetSymbolAddress((void**)&qkv, g_qkv);
    cudaGetSymbolAddress((void**)&hid_hi, g_hid_hi);
    cudaGetSymbolAddress((void**)&hid_lo, g_hid_lo);
    cudaGetSymbolAddress((void**)&wqkv_hi, g_wqkv_hi);
    cudaGetSymbolAddress((void**)&wqkv_lo, g_wqkv_lo);
    cudaGetSymbolAddress((void**)&attn_hi, g_attn_hi);
    cudaGetSymbolAddress((void**)&attn_lo, g_attn_lo);
    cudaGetSymbolAddress((void**)&wout_hi, g_wout_hi);
    cudaGetSymbolAddress((void**)&wout_lo, g_wout_lo);
    cudaGetSymbolAddress((void**)&q_hi, g_q_hi);
    cudaGetSymbolAddress((void**)&q_lo, g_q_lo);
    cudaGetSymbolAddress((void**)&k_hi, g_k_hi);
    cudaGetSymbolAddress((void**)&k_lo, g_k_lo);
    cudaGetSymbolAddress((void**)&v_hi, g_v_hi);
    cudaGetSymbolAddress((void**)&v_lo, g_v_lo);

    // Splits for GEMM inputs
    {
        int n1 = T * HID;
        split_kernel<<<n1 / 1024, 256>>>(hidden, hid_hi, hid_lo, n1);
        int n2 = HID * QKV_COLS;
        split_kernel<<<n2 / 1024, 256>>>(w_qkv, wqkv_hi, wqkv_lo, n2);
        int n3 = NQ * HD * HID;
        split_kernel<<<n3 / 1024, 256>>>(w_out, wout_hi, wout_lo, n3);
    }

    cudaFuncSetAttribute(gemm_bf16x3,
                         cudaFuncAttributeMaxDynamicSharedMemorySize, G_SMEM_BYTES);

    // 1) QKV projection
    {
        dim3 grid(QKV_COLS / GBN, T / GBM);
        gemm_bf16x3<<<grid, 256, G_SMEM_BYTES>>>(hid_hi, hid_lo, wqkv_hi, wqkv_lo,
                                                 qkv, T, QKV_COLS, HID);
    }

    // 2) RMSNorm + RoPE + split (q scaled by 1/8)
    {
        int nwarps = T * (NQ + 2 * NKV);
        norm_rope_split_kernel<<<nwarps / 8, 256>>>(qkv, positions, q_ln_w, k_ln_w,
                                                    q_hi, q_lo, k_hi, k_lo, v_hi, v_lo);
    }

    // 3) Tensor-core causal attention -> attn hi/lo directly
    {
        cudaFuncSetAttribute(attn_mma_kernel,
                             cudaFuncAttributeMaxDynamicSharedMemorySize, A_SMEM_BYTES);
        dim3 grid(T / 128, NQ);
        attn_mma_kernel<<<grid, 256, A_SMEM_BYTES>>>(q_hi, q_lo, k_hi, k_lo,
                                                     v_hi, v_lo, attn_hi, attn_lo);
    }

    // 4) Output projection
    {
        dim3 grid(HID / GBN, T / GBM);
        gemm_bf16x3<<<grid, 256, G_SMEM_BYTES>>>(attn_hi, attn_lo, wout_hi, wout_lo,
                                                 out, T, HID, NQ * HD);
    }
}